// round 14
// baseline (speedup 1.0000x reference)
#include <cuda_runtime.h>
#include <math.h>

#define LEAKY_SLOPE 0.01f
#define EPS_C 0.1f
#define GAMMA_C 0.1f

#define NN 50000
#define EE 600000

// ---------------- scratch (node/edge data only; NO weight-copy arrays) ----------------
__device__ __align__(16) float g_h   [NN * 128];
__device__ __align__(16) float g_h2  [NN * 64];
__device__ __align__(16) float g_buf [NN * 256];   // fused [msg | anti] rows
__device__ int   g_deg   [NN];
__device__ float g_dinv  [NN];
__device__ int   g_src   [EE];
__device__ int   g_dst   [EE];
__device__ int   g_rowptr[NN + 1];
__device__ int   g_cursor[NN];
__device__ int   g_colidx[EE];
__device__ int   g_is64;

__device__ __forceinline__ float lky(float x) { return x > 0.f ? x : LEAKY_SLOPE * x; }
__device__ __forceinline__ int clampN(int v) { return v < 0 ? 0 : (v >= NN ? NN - 1 : v); }

// ---------------- packed fp32x2 helpers ----------------
__device__ __forceinline__ unsigned long long pk(float lo, float hi) {
    unsigned long long r;
    asm("mov.b64 %0, {%1,%2};" : "=l"(r) : "f"(lo), "f"(hi));
    return r;
}
__device__ __forceinline__ void upk(unsigned long long v, float& lo, float& hi) {
    asm("mov.b64 {%0,%1}, %2;" : "=f"(lo), "=f"(hi) : "l"(v));
}
__device__ __forceinline__ void fma2(unsigned long long& d, unsigned long long a,
                                     unsigned long long b) {
    asm("fma.rn.f32x2 %0, %1, %2, %0;" : "+l"(d) : "l"(a), "l"(b));
}

// ---------------- probe (launch #1) ----------------
__global__ void probe_kernel(const unsigned int* __restrict__ w) {
    __shared__ int fl;
    if (threadIdx.x == 0) fl = 0;
    __syncthreads();
    for (int i = 1 + 2 * (int)threadIdx.x; i < 16384; i += 2 * (int)blockDim.x)
        if (w[i] != 0u) fl = 1;
    __syncthreads();
    if (threadIdx.x == 0) g_is64 = (fl == 0) ? 1 : 0;
}

// ---------------- convert + zero_deg fused (launch #2) ----------------
__global__ void convert_zero(const void* __restrict__ raw) {
    int i = blockIdx.x * blockDim.x + threadIdx.x;
    if (i < NN) g_deg[i] = 0;
    if (i >= EE) return;
    int s, d;
    if (g_is64) {
        const long long* p = (const long long*)raw;
        s = (int)p[i];
        d = (int)p[EE + i];
    } else {
        const int* p = (const int*)raw;
        s = p[i];
        d = p[EE + i];
    }
    g_src[i] = clampN(s);
    g_dst[i] = clampN(d);
}

// ---------------- hist (launch #3) ----------------
__global__ void hist_kernel() {
    int i = blockIdx.x * blockDim.x + threadIdx.x;
    if (i < EE) atomicAdd(&g_deg[g_dst[i]], 1);
}

// ---------------- degree norm ----------------
__global__ void dinv_kernel() {
    int i = blockIdx.x * blockDim.x + threadIdx.x;
    if (i < NN) g_dinv[i] = rsqrtf((float)(g_deg[i] + 1));  // +1 self loop
}

// ---------------- CSR scan (writes rowptr AND cursor) ----------------
__global__ void scan_kernel() {
    __shared__ int sh[1024];
    __shared__ int carry;
    int t = threadIdx.x;
    if (t == 0) carry = 0;
    __syncthreads();
    for (int base = 0; base < NN; base += 1024) {
        int v = (base + t < NN) ? g_deg[base + t] : 0;
        sh[t] = v;
        __syncthreads();
        for (int off = 1; off < 1024; off <<= 1) {
            int add = (t >= off) ? sh[t - off] : 0;
            __syncthreads();
            sh[t] += add;
            __syncthreads();
        }
        int incl = sh[t];
        int excl = carry + incl - v;
        if (base + t < NN) {
            g_rowptr[base + t] = excl;
            g_cursor[base + t] = excl;
        }
        __syncthreads();
        if (t == 1023) carry += incl;
        __syncthreads();
    }
    if (t == 0) g_rowptr[NN] = carry;
}
__global__ void fill_kernel() {
    int i = blockIdx.x * blockDim.x + threadIdx.x;
    if (i >= EE) return;
    int d = g_dst[i];
    int p = atomicAdd(&g_cursor[d], 1);
    if (p < EE) g_colidx[p] = g_src[i];
}

// ---------------- GEMM v4 (verbatim R13): 128x64, 8x4/thread, dbl-buffered, FFMA2 --------
template<int K, int J, int BMODE, int PREL, int POSTL>
__global__ void __launch_bounds__(256)
gemm_kernel(const float* __restrict__ A, const float* __restrict__ W1,
            const float* __restrict__ W2, const float* __restrict__ bias,
            float* __restrict__ C) {
    __shared__ float sA[2][16][132];
    __shared__ float sB[2][16][64];
    const int tid = threadIdx.x;
    const int tx = tid & 15;
    const int ty = tid >> 4;
    const int row0 = blockIdx.x * 128;
    const int col0 = blockIdx.y * 64;
    constexpr int HALF = J / 2;
    constexpr int NT = K / 16;

    const int ar0 = tid >> 2;
    const int ak4 = (tid & 3) * 4;
    const int jloc0 = tid >> 2;
    const int kloc0 = (tid & 3) * 4;
    const int kB1 = tid >> 4;
    const int jB1 = (tid & 15) * 4;

    float4 stA0, stA1, stB;
    unsigned long long acc[4][4];
#pragma unroll
    for (int p = 0; p < 4; p++)
#pragma unroll
        for (int c = 0; c < 4; c++) acc[p][c] = 0ull;

    auto prefetch = [&](int kt) {
        {
            float4 v = make_float4(0.f, 0.f, 0.f, 0.f);
            int gr = row0 + ar0;
            if (gr < NN) v = *(const float4*)(A + (size_t)gr * K + kt + ak4);
            if (PREL) { v.x = lky(v.x); v.y = lky(v.y); v.z = lky(v.z); v.w = lky(v.w); }
            stA0 = v;
        }
        {
            float4 v = make_float4(0.f, 0.f, 0.f, 0.f);
            int gr = row0 + ar0 + 64;
            if (gr < NN) v = *(const float4*)(A + (size_t)gr * K + kt + ak4);
            if (PREL) { v.x = lky(v.x); v.y = lky(v.y); v.z = lky(v.z); v.w = lky(v.w); }
            stA1 = v;
        }
        if (BMODE == 0) {
            int j = col0 + jloc0;
            stB = *(const float4*)(W1 + (size_t)j * K + kt + kloc0);
        } else {
            int kk = kt + kB1;
            float b[4];
#pragma unroll
            for (int i = 0; i < 4; i++) {
                int j = col0 + jB1 + i;
                if (j < HALF) {
                    b[i] = W1[(size_t)kk * HALF + j];
                } else {
                    int jj = j - HALF;
                    b[i] = W2[(size_t)jj * HALF + kk] - W2[(size_t)kk * HALF + jj]
                         - ((kk == jj) ? GAMMA_C : 0.f);
                }
            }
            stB = make_float4(b[0], b[1], b[2], b[3]);
        }
    };
    auto commit = [&](int buf) {
        sA[buf][ak4 + 0][ar0] = stA0.x;
        sA[buf][ak4 + 1][ar0] = stA0.y;
        sA[buf][ak4 + 2][ar0] = stA0.z;
        sA[buf][ak4 + 3][ar0] = stA0.w;
        sA[buf][ak4 + 0][ar0 + 64] = stA1.x;
        sA[buf][ak4 + 1][ar0 + 64] = stA1.y;
        sA[buf][ak4 + 2][ar0 + 64] = stA1.z;
        sA[buf][ak4 + 3][ar0 + 64] = stA1.w;
        if (BMODE == 0) {
            sB[buf][kloc0 + 0][jloc0] = stB.x;
            sB[buf][kloc0 + 1][jloc0] = stB.y;
            sB[buf][kloc0 + 2][jloc0] = stB.z;
            sB[buf][kloc0 + 3][jloc0] = stB.w;
        } else {
            *(float4*)&sB[buf][kB1][jB1] = stB;
        }
    };

    prefetch(0);
    commit(0);
    __syncthreads();

    int cur = 0;
#pragma unroll 1
    for (int t = 0; t < NT; t++) {
        if (t + 1 < NT) prefetch((t + 1) * 16);
#pragma unroll
        for (int k = 0; k < 16; k++) {
            float4 va = *(const float4*)&sA[cur][k][ty * 8];
            float4 vb = *(const float4*)&sA[cur][k][ty * 8 + 4];
            float4 bb = *(const float4*)&sB[cur][k][tx * 4];
            unsigned long long ap0 = pk(va.x, va.y);
            unsigned long long ap1 = pk(va.z, va.w);
            unsigned long long ap2 = pk(vb.x, vb.y);
            unsigned long long ap3 = pk(vb.z, vb.w);
            unsigned long long b0 = pk(bb.x, bb.x);
            unsigned long long b1 = pk(bb.y, bb.y);
            unsigned long long b2 = pk(bb.z, bb.z);
            unsigned long long b3 = pk(bb.w, bb.w);
            fma2(acc[0][0], ap0, b0); fma2(acc[0][1], ap0, b1);
            fma2(acc[0][2], ap0, b2); fma2(acc[0][3], ap0, b3);
            fma2(acc[1][0], ap1, b0); fma2(acc[1][1], ap1, b1);
            fma2(acc[1][2], ap1, b2); fma2(acc[1][3], ap1, b3);
            fma2(acc[2][0], ap2, b0); fma2(acc[2][1], ap2, b1);
            fma2(acc[2][2], ap2, b2); fma2(acc[2][3], ap2, b3);
            fma2(acc[3][0], ap3, b0); fma2(acc[3][1], ap3, b1);
            fma2(acc[3][2], ap3, b2); fma2(acc[3][3], ap3, b3);
        }
        if (t + 1 < NT) {
            commit(cur ^ 1);
            __syncthreads();
            cur ^= 1;
        }
    }

    float4 bv = make_float4(0.f, 0.f, 0.f, 0.f);
    if (bias) bv = *(const float4*)(bias + col0 + tx * 4);
#pragma unroll
    for (int p = 0; p < 4; p++) {
        float l0, h0, l1, h1, l2, h2, l3, h3;
        upk(acc[p][0], l0, h0);
        upk(acc[p][1], l1, h1);
        upk(acc[p][2], l2, h2);
        upk(acc[p][3], l3, h3);
        int rl = row0 + ty * 8 + 2 * p;
        if (rl < NN) {
            float4 o = make_float4(l0 + bv.x, l1 + bv.y, l2 + bv.z, l3 + bv.w);
            if (POSTL) { o.x = lky(o.x); o.y = lky(o.y); o.z = lky(o.z); o.w = lky(o.w); }
            *(float4*)(C + (size_t)rl * J + col0 + tx * 4) = o;
        }
        int rh = rl + 1;
        if (rh < NN) {
            float4 o = make_float4(h0 + bv.x, h1 + bv.y, h2 + bv.z, h3 + bv.w);
            if (POSTL) { o.x = lky(o.x); o.y = lky(o.y); o.z = lky(o.z); o.w = lky(o.w); }
            *(float4*)(C + (size_t)rh * J + col0 + tx * 4) = o;
        }
    }
}

// ---------------- gather+update v2: H/32 warps per node, one j per lane, unroll x4 --------
// agg_j = msg[i][j]*di*di + sum_{s in CSR order} msg[s][j]*dinv[s]*di   (same FP order per j)
template<int H, int RS>
__global__ void __launch_bounds__(256) k_gather_update(float* __restrict__ h,
                                                       const float* __restrict__ buf,
                                                       const float* __restrict__ bias) {
    constexpr int QW = H / 32;                       // warps per node (4 or 2)
    int gw = (blockIdx.x * blockDim.x + threadIdx.x) >> 5;
    int node = gw / QW;
    int q = gw - node * QW;
    if (node >= NN) return;
    int lane = threadIdx.x & 31;
    int j = q * 32 + lane;

    float di = g_dinv[node];
    const float* base = buf + (size_t)node * RS;
    float acc = base[j] * di * di;                   // self loop

    int e0 = g_rowptr[node], e1 = g_rowptr[node + 1];
    int e = e0;
    for (; e + 3 < e1; e += 4) {
        int s0 = g_colidx[e + 0];
        int s1 = g_colidx[e + 1];
        int s2 = g_colidx[e + 2];
        int s3 = g_colidx[e + 3];
        float w0 = g_dinv[s0] * di;
        float w1 = g_dinv[s1] * di;
        float w2 = g_dinv[s2] * di;
        float w3 = g_dinv[s3] * di;
        float v0 = buf[(size_t)s0 * RS + j];
        float v1 = buf[(size_t)s1 * RS + j];
        float v2 = buf[(size_t)s2 * RS + j];
        float v3 = buf[(size_t)s3 * RS + j];
        acc = fmaf(v3, w3, fmaf(v2, w2, fmaf(v1, w1, fmaf(v0, w0, acc))));
    }
    for (; e < e1; e++) {
        int s = g_colidx[e];
        float w = g_dinv[s] * di;
        acc = fmaf(buf[(size_t)s * RS + j], w, acc);
    }

    float a = base[H + j];                           // anti half (includes -gamma*h)
    size_t idx = (size_t)node * H + j;
    h[idx] += EPS_C * tanhf(a + acc + bias[j]);
}

// ---------------- fc + log_softmax v2: 128 nodes/block, smem-staged, coalesced ----------
__global__ void __launch_bounds__(128) k_fc(const float* __restrict__ h2,
                                            const float* __restrict__ wfc,
                                            const float* __restrict__ bfc,
                                            float* __restrict__ out) {
    __shared__ float sh[128 * 65];       // h2 tile, padded stride 65 (conflict-free)
    __shared__ float swf[40 * 64];       // weights
    int tid = threadIdx.x;
    int nb = blockIdx.x * 128;

    // stage h2 tile (coalesced float4 loads)
    const float4* h2v = (const float4*)h2;
    for (int t = tid; t < 128 * 16; t += 128) {
        int n = t >> 4;
        int off = (t & 15) * 4;
        float4 v = make_float4(0.f, 0.f, 0.f, 0.f);
        if (nb + n < NN) v = h2v[(size_t)(nb + n) * 16 + (t & 15)];
        sh[n * 65 + off + 0] = v.x;
        sh[n * 65 + off + 1] = v.y;
        sh[n * 65 + off + 2] = v.z;
        sh[n * 65 + off + 3] = v.w;
    }
    // stage weights
    for (int t = tid; t < 40 * 64; t += 128) swf[t] = wfc[t];
    __syncthreads();

    int i = nb + tid;
    if (i >= NN) return;

    float acc[40];
#pragma unroll
    for (int j = 0; j < 40; j++) acc[j] = bfc[j];
#pragma unroll 4
    for (int k = 0; k < 64; k++) {
        float hk = sh[tid * 65 + k];
#pragma unroll
        for (int j = 0; j < 40; j++)
            acc[j] = fmaf(hk, swf[j * 64 + k], acc[j]);
    }
    float m = -1e30f;
#pragma unroll
    for (int j = 0; j < 40; j++) m = fmaxf(m, acc[j]);
    float s = 0.f;
#pragma unroll
    for (int j = 0; j < 40; j++) s += expf(acc[j] - m);
    float lse = m + logf(s);
    float* o = out + (size_t)i * 40;
#pragma unroll
    for (int j = 0; j < 40; j++) o[j] = acc[j] - lse;
}

// ---------------- launch (layer0 GEMM at capture slot #4) ----------------
extern "C" void kernel_launch(void* const* d_in, const int* in_sizes, int n_in,
                              void* d_out, int out_size) {
    const float* x      = (const float*)d_in[0];
    const void*  edges  = d_in[1];
    const float* w_hid  = (const float*)d_in[2];
    const float* b_hid  = (const float*)d_in[3];
    const float* W_a1   = (const float*)d_in[4];
    const float* gcn_w1 = (const float*)d_in[5];
    const float* b_a1   = (const float*)d_in[6];
    const float* w_hid2 = (const float*)d_in[7];
    const float* b_hid2 = (const float*)d_in[8];
    const float* W_a2   = (const float*)d_in[9];
    const float* gcn_w2 = (const float*)d_in[10];
    const float* b_a2   = (const float*)d_in[11];
    const float* w_fc   = (const float*)d_in[12];
    const float* b_fc   = (const float*)d_in[13];
    float* out = (float*)d_out;

    int gx = (NN + 127) / 128;                 // 391
    int cvtBlocks = ((EE > NN ? EE : NN) + 255) / 256;
    // gather grids: H=128 -> 4 warps/node, H=64 -> 2 warps/node
    int gBlocks128 = ((NN * 4) * 32 + 255) / 256;
    int gBlocks64  = ((NN * 2) * 32 + 255) / 256;

    // #1..#3
    probe_kernel<<<1, 1024>>>((const unsigned int*)edges);
    convert_zero<<<cvtBlocks, 256>>>(edges);
    hist_kernel<<<(EE + 255) / 256, 256>>>();

    // #4: layer0 GEMM  [N,256]->[N,128]   (ncu capture target)
    gemm_kernel<256, 128, 0, 0, 1><<<dim3(gx, 2), 256>>>(x, w_hid, nullptr, b_hid, g_h);

    // rest of preprocessing
    dinv_kernel<<<(NN + 255) / 256, 256>>>();
    scan_kernel<<<1, 1024>>>();
    fill_kernel<<<(EE + 255) / 256, 256>>>();

    // conv1: 3 iterations, H=128
    for (int it = 0; it < 3; it++) {
        gemm_kernel<128, 256, 1, 0, 0><<<dim3(gx, 4), 256>>>(g_h, gcn_w1, W_a1, nullptr, g_buf);
        k_gather_update<128, 256><<<gBlocks128, 256>>>(g_h, g_buf, b_a1);
    }

    // hid2  [N,128]->[N,64]
    gemm_kernel<128, 64, 0, 1, 1><<<dim3(gx, 1), 256>>>(g_h, w_hid2, nullptr, b_hid2, g_h2);

    // conv2: 1 iteration, H=64
    gemm_kernel<64, 128, 1, 0, 0><<<dim3(gx, 2), 256>>>(g_h2, gcn_w2, W_a2, nullptr, g_buf);
    k_gather_update<64, 128><<<gBlocks64, 256>>>(g_h2, g_buf, b_a2);

    // fc + log_softmax
    k_fc<<<(NN + 127) / 128, 128>>>(g_h2, w_fc, b_fc, out);
}